// round 16
// baseline (speedup 1.0000x reference)
#include <cuda_runtime.h>
#include <cuda_bf16.h>
#include <math.h>
#include <stdint.h>

#define BB 4
#define NN 1024
#define MM 1024
#define DD 1024
#define HH 16
#define HD 64

typedef __nv_bfloat16 bf16;

// ---------------------------------------------------------------------------
// Device scratch (no allocation allowed)
// ---------------------------------------------------------------------------
__device__ float g_Q[BB * NN * DD];                 // Q[b,n,h*64+d] (proj out)
__device__ float g_KV[BB * MM * 2 * DD];            // KV[b,m,c,h*64+d] (proj out)
__device__ float g_Pt[(size_t)BB * HH * NN * MM];   // exp'd probabilities [b,h,n,m]
__device__ float g_O[BB * NN * DD];                 // O[b,n,h*64+d]
__device__ bf16 g_WqTh[DD * DD], g_WqTl[DD * DD];          // Wq^T planes [out,in]
__device__ bf16 g_WkvTh[2 * DD * DD], g_WkvTl[2 * DD * DD];
__device__ bf16 g_Xh[BB * NN * DD], g_Xl[BB * NN * DD];    // input planes (reused)
__device__ bf16 g_Qph[BB * HH * NN * HD], g_Qpl[BB * HH * NN * HD];  // [b,h,n,d]
__device__ bf16 g_Kph[BB * HH * MM * HD], g_Kpl[BB * HH * MM * HD];  // [b,h,m,d]
__device__ bf16 g_Vth[BB * HH * HD * MM], g_Vtl[BB * HH * HD * MM];  // [b,h,d,m]
__device__ float g_maskadd[BB * MM];

#define TRANS_SMEM (16 * 1025 * 4)

// ---------------------------------------------------------------------------
// helpers
// ---------------------------------------------------------------------------
__device__ __forceinline__ uint32_t smem_to_u32(const void* p) {
    uint32_t a;
    asm("{ .reg .u64 t; cvta.to.shared.u64 t, %1; cvt.u32.u64 %0, t; }" : "=r"(a) : "l"(p));
    return a;
}
#define CP16(dst, src) \
    asm volatile("cp.async.cg.shared.global [%0], [%1], 16;" :: "r"(dst), "l"(src) : "memory")
#define CP_COMMIT() asm volatile("cp.async.commit_group;" ::: "memory")
#define CP_WAIT1() asm volatile("cp.async.wait_group 1;" ::: "memory")

__device__ __forceinline__ void bf16split2(float x, float y, uint32_t& h, uint32_t& l) {
    __nv_bfloat162 hb = __floats2bfloat162_rn(x, y);
    float rx = x - __bfloat162float(hb.x);
    float ry = y - __bfloat162float(hb.y);
    __nv_bfloat162 lb = __floats2bfloat162_rn(rx, ry);
    h = *(uint32_t*)&hb;
    l = *(uint32_t*)&lb;
}
__device__ __forceinline__ void split_bf16(float x, bf16& h, bf16& l) {
    h = __float2bfloat16_rn(x);
    l = __float2bfloat16_rn(x - __bfloat162float(h));
}
__device__ __forceinline__ void mma_bf16(float* c, const uint32_t* a, const uint32_t* b) {
    asm volatile(
        "mma.sync.aligned.m16n8k16.row.col.f32.bf16.bf16.f32 "
        "{%0,%1,%2,%3}, {%4,%5,%6,%7}, {%8,%9}, {%0,%1,%2,%3};"
        : "+f"(c[0]), "+f"(c[1]), "+f"(c[2]), "+f"(c[3])
        : "r"(a[0]), "r"(a[1]), "r"(a[2]), "r"(a[3]), "r"(b[0]), "r"(b[1]));
}
__device__ __forceinline__ void ldsm_x4(uint32_t& r0, uint32_t& r1, uint32_t& r2,
                                        uint32_t& r3, uint32_t addr) {
    asm volatile("ldmatrix.sync.aligned.m8n8.x4.shared.b16 {%0,%1,%2,%3}, [%4];"
                 : "=r"(r0), "=r"(r1), "=r"(r2), "=r"(r3) : "r"(addr));
}

// Fast exp on fma/alu pipes (no MUFU).
__device__ __forceinline__ float fexp(float x) {
    x = fmaxf(x, -87.0f);
    float t = x * 1.44269504088896f;
    float z = t + 12582912.0f;
    float nf = z - 12582912.0f;
    float f = t - nf;
    int sc = (((int)nf) + 127) << 23;
    float p = 0.009618129f;
    p = fmaf(p, f, 0.055490663f);
    p = fmaf(p, f, 0.240226507f);
    p = fmaf(p, f, 0.693147181f);
    p = fmaf(p, f, 1.0f);
    return p * __int_as_float(sc);
}

// ---------------------------------------------------------------------------
// Projection GEMM: all operands pre-split bf16 planes, cp.async 3-stage
// pipeline, ldmatrix fragments, 3-term MMA (ILP-reordered).
// C[128 x 128 tile] = A @ B^T + bias (f32 out).
// smem stage (u32): Ah[128*20] Al Bh Bl  -> 40KB/stage, 3 stages.
// ---------------------------------------------------------------------------
#define P_ALOFF (128 * 20)
#define P_BOFF (2 * 128 * 20)
#define P_BLOFF (3 * 128 * 20)
#define P_STAGE (4 * 128 * 20)

__global__ void __launch_bounds__(256, 1)
gemm_proj_kernel(const bf16* __restrict__ Ah0, const bf16* __restrict__ Al0,
                 const bf16* __restrict__ Bh0, const bf16* __restrict__ Bl0,
                 const float* __restrict__ bias, float* __restrict__ C, long ldc) {
    extern __shared__ uint32_t smem_u[];
    int tid = threadIdx.x, wid = tid >> 5, lane = tid & 31;
    int row0 = blockIdx.x * 128, col0 = blockIdx.y * 128;
    int wc = wid & 3, wr = wid >> 2;
    int g = lane >> 2, t = lane & 3;
    uint32_t smem0 = smem_to_u32(smem_u);

    const bf16* Ah = Ah0 + (size_t)row0 * DD;
    const bf16* Al = Al0 + (size_t)row0 * DD;
    const bf16* Bh = Bh0 + (size_t)col0 * DD;
    const bf16* Bl = Bl0 + (size_t)col0 * DD;

    // issue one K-stage: 128 rows x 64B per plane, A(h,l) + B(h,l)
    auto issue = [&](int buf, int k0) {
        uint32_t base = smem0 + buf * (P_STAGE * 4);
        for (int i = tid; i < 1024; i += 256) {
            int r = i >> 3, c = i & 7;
            int pl = c >> 2, ch = c & 3;
            uint32_t doff = (uint32_t)(r * 80 + ch * 16);
            size_t soff = (size_t)r * DD + k0 + ch * 8;
            CP16(base + (pl ? P_ALOFF * 4 : 0) + doff, (pl ? Al : Ah) + soff);
            CP16(base + (pl ? P_BLOFF * 4 : P_BOFF * 4) + doff, (pl ? Bl : Bh) + soff);
        }
    };

    uint32_t aoff_lane = (uint32_t)(lane & 15) * 80 + (lane >> 4) * 16;
    uint32_t boff_lane = (uint32_t)((((lane >> 4) & 1) * 8 + (lane & 7)) * 80) +
                         ((lane >> 3) & 1) * 16;

    float acc[4][4][4] = {};
    issue(0, 0);
    CP_COMMIT();
    issue(1, 32);
    CP_COMMIT();

    for (int kt = 0; kt < 32; kt++) {
        CP_WAIT1();
        __syncthreads();
        if (kt + 2 < 32) issue((kt + 2) % 3, (kt + 2) << 5);
        CP_COMMIT();

        uint32_t stb = smem0 + (kt % 3) * (P_STAGE * 4);
#pragma unroll
        for (int kk = 0; kk < 2; kk++) {
            uint32_t kb = kk * 32;
            uint32_t bh[4][2], bl[4][2];
            uint32_t bb = stb + P_BOFF * 4 + (uint32_t)(wc * 32 * 80) + kb + boff_lane;
            ldsm_x4(bh[0][0], bh[0][1], bh[1][0], bh[1][1], bb);
            ldsm_x4(bh[2][0], bh[2][1], bh[3][0], bh[3][1], bb + 16 * 80);
            ldsm_x4(bl[0][0], bl[0][1], bl[1][0], bl[1][1], bb + 128 * 20 * 4);
            ldsm_x4(bl[2][0], bl[2][1], bl[3][0], bl[3][1], bb + 128 * 20 * 4 + 16 * 80);
#pragma unroll
            for (int mi = 0; mi < 4; mi++) {
                uint32_t ab = stb + (uint32_t)((wr * 64 + mi * 16) * 80) + kb + aoff_lane;
                uint32_t ah[4], al[4];
                ldsm_x4(ah[0], ah[1], ah[2], ah[3], ab);
                ldsm_x4(al[0], al[1], al[2], al[3], ab + P_ALOFF * 4);
#pragma unroll
                for (int ni = 0; ni < 4; ni++) mma_bf16(acc[mi][ni], ah, bh[ni]);
#pragma unroll
                for (int ni = 0; ni < 4; ni++) mma_bf16(acc[mi][ni], ah, bl[ni]);
#pragma unroll
                for (int ni = 0; ni < 4; ni++) mma_bf16(acc[mi][ni], al, bh[ni]);
            }
        }
        __syncthreads();
    }

#pragma unroll
    for (int mi = 0; mi < 4; mi++) {
#pragma unroll
        for (int ni = 0; ni < 4; ni++) {
            int row = row0 + wr * 64 + mi * 16 + g;
            int col = col0 + wc * 32 + ni * 8 + 2 * t;
            float2 bb = *(const float2*)(bias + col);
            float2 v0 = make_float2(acc[mi][ni][0] + bb.x, acc[mi][ni][1] + bb.y);
            float2 v1 = make_float2(acc[mi][ni][2] + bb.x, acc[mi][ni][3] + bb.y);
            *(float2*)(C + (size_t)row * ldc + col) = v0;
            *(float2*)(C + (size_t)(row + 8) * ldc + col) = v1;
        }
    }
}

// ---------------------------------------------------------------------------
// f32 -> bf16 hi/lo planes (R8-validated)
// ---------------------------------------------------------------------------
__global__ void convert_split_kernel(const float* __restrict__ src,
                                     bf16* __restrict__ dh, bf16* __restrict__ dl, int n4) {
    int i = blockIdx.x * 256 + threadIdx.x;
    if (i >= n4) return;
    float4 v = ((const float4*)src)[i];
    uint32_t h0, l0, h1, l1;
    bf16split2(v.x, v.y, h0, l0);
    bf16split2(v.z, v.w, h1, l1);
    ((uint32_t*)dh)[i * 2] = h0;
    ((uint32_t*)dh)[i * 2 + 1] = h1;
    ((uint32_t*)dl)[i * 2] = l0;
    ((uint32_t*)dl)[i * 2 + 1] = l1;
}

// ---------------------------------------------------------------------------
// Weight transpose -> planes (R8-validated): d*[c][r] = split(src[r][c])
// ---------------------------------------------------------------------------
__global__ void transposeW_planes(const float* __restrict__ src,
                                  bf16* __restrict__ dh, bf16* __restrict__ dl,
                                  int rows, int cols) {
    __shared__ float tbuf[32][33];
    int c0 = blockIdx.x * 32, r0 = blockIdx.y * 32;
    int tx = threadIdx.x, ty = threadIdx.y;
    for (int i = ty; i < 32; i += 8) tbuf[i][tx] = src[(size_t)(r0 + i) * cols + c0 + tx];
    __syncthreads();
    for (int i = ty; i < 32; i += 8) {
        bf16 h, l;
        split_bf16(tbuf[tx][i], h, l);
        size_t o = (size_t)(c0 + i) * rows + r0 + tx;
        dh[o] = h;
        dl[o] = l;
    }
}

// ---------------------------------------------------------------------------
// Fused attention (R15 verbatim)
// ---------------------------------------------------------------------------
#define S_PITCH 1034
#define S_OFF 0
#define QH_OFF (32 * S_PITCH)
#define QL_OFF (QH_OFF + 32 * 36)
#define KV_OFF (QL_OFF + 32 * 36)
#define KV_PLANE 4608
#define KV_BUF (2 * KV_PLANE)
#define MASK_OFF (KV_OFF + 2 * KV_BUF)
#define FUSED_U32 (MASK_OFF + 1024)
#define FUSED_SMEM (FUSED_U32 * 4)

__global__ void __launch_bounds__(256, 1) attn_fused_kernel() {
    extern __shared__ uint32_t su[];
    __shared__ float s_inv32[32];

    int tid = threadIdx.x, wid = tid >> 5, lane = tid & 31;
    int z = blockIdx.z;
    int b = z >> 4;
    int n0 = blockIdx.x * 32;
    int wr = wid >> 2, wc = wid & 3;
    int g = lane >> 2, t = lane & 3;
    uint32_t smem0 = smem_to_u32(su);

    const uint32_t* Qh32 = (const uint32_t*)g_Qph + ((size_t)z * NN + n0) * 32;
    const uint32_t* Ql32 = (const uint32_t*)g_Qpl + ((size_t)z * NN + n0) * 32;
    const bf16* Khp = g_Kph + (size_t)z * MM * HD;
    const bf16* Klp = g_Kpl + (size_t)z * MM * HD;
    const bf16* Vhp = g_Vth + (size_t)z * HD * MM;
    const bf16* Vlp = g_Vtl + (size_t)z * HD * MM;
    float* Prow = g_Pt + ((size_t)z * NN + n0) * MM;

    for (int i = tid; i < 32 * 32; i += 256) {
        int r = i >> 5, j = i & 31;
        su[QH_OFF + r * 36 + j] = Qh32[r * 32 + j];
        su[QL_OFF + r * 36 + j] = Ql32[r * 32 + j];
    }
    for (int i = tid; i < 1024; i += 256)
        ((float*)su)[MASK_OFF + i] = g_maskadd[b * MM + i];

    uint32_t koff_lane = (uint32_t)((((lane >> 4) & 1) * 8 + (lane & 7)) * 144) +
                         ((lane >> 3) & 1) * 16;
    uint32_t voff_lane = (uint32_t)((((lane >> 4) & 1) * 8 + (lane & 7)) * 272) +
                         ((lane >> 3) & 1) * 16;

    auto issueK = [&](int buf, int ch) {
        uint32_t base = smem0 + (KV_OFF + buf * KV_BUF) * 4;
        int m0 = ch << 7;
        for (int i = tid; i < 1024; i += 256) {
            int r = i >> 3, sg = i & 7;
            uint32_t d = base + (uint32_t)(r * 36 + sg * 4) * 4;
            CP16(d, Khp + (size_t)(m0 + r) * HD + sg * 8);
            CP16(d + KV_PLANE * 4, Klp + (size_t)(m0 + r) * HD + sg * 8);
        }
    };

    issueK(0, 0);
    CP_COMMIT();
    __syncthreads();

    uint32_t qh[4][4], ql[4][4];
#pragma unroll
    for (int kk = 0; kk < 4; kk++) {
        int r = wr * 16 + g;
        int p = r * 36 + kk * 8 + t;
        qh[kk][0] = su[QH_OFF + p];          qh[kk][2] = su[QH_OFF + p + 4];
        qh[kk][1] = su[QH_OFF + p + 8 * 36]; qh[kk][3] = su[QH_OFF + p + 8 * 36 + 4];
        ql[kk][0] = su[QL_OFF + p];          ql[kk][2] = su[QL_OFF + p + 4];
        ql[kk][1] = su[QL_OFF + p + 8 * 36]; ql[kk][3] = su[QL_OFF + p + 8 * 36 + 4];
    }

    for (int ch = 0; ch < 8; ch++) {
        if (ch < 7) issueK((ch + 1) & 1, ch + 1);
        CP_COMMIT();
        CP_WAIT1();
        __syncthreads();

        uint32_t kvb = smem0 + (KV_OFF + (ch & 1) * KV_BUF) * 4;
        float acc[4][4] = {};
#pragma unroll
        for (int kk = 0; kk < 4; kk++) {
            uint32_t bh[4][2], bl[4][2];
            uint32_t bb = kvb + (uint32_t)(wc * 32 * 144) + kk * 32 + koff_lane;
            ldsm_x4(bh[0][0], bh[0][1], bh[1][0], bh[1][1], bb);
            ldsm_x4(bh[2][0], bh[2][1], bh[3][0], bh[3][1], bb + 16 * 144);
            ldsm_x4(bl[0][0], bl[0][1], bl[1][0], bl[1][1], bb + KV_PLANE * 4);
            ldsm_x4(bl[2][0], bl[2][1], bl[3][0], bl[3][1], bb + KV_PLANE * 4 + 16 * 144);
#pragma unroll
            for (int ni = 0; ni < 4; ni++) mma_bf16(acc[ni], qh[kk], bh[ni]);
#pragma unroll
            for (int ni = 0; ni < 4; ni++) mma_bf16(acc[ni], qh[kk], bl[ni]);
#pragma unroll
            for (int ni = 0; ni < 4; ni++) mma_bf16(acc[ni], ql[kk], bh[ni]);
        }
        int m0 = ch << 7;
        float* Sf = (float*)su;
#pragma unroll
        for (int ni = 0; ni < 4; ni++) {
            int col = m0 + wc * 32 + ni * 8 + 2 * t;
            float mk0 = ((float*)su)[MASK_OFF + col];
            float mk1 = ((float*)su)[MASK_OFF + col + 1];
            int r0 = wr * 16 + g;
            Sf[S_OFF + r0 * S_PITCH + col] = acc[ni][0] * 0.125f + mk0;
            Sf[S_OFF + r0 * S_PITCH + col + 1] = acc[ni][1] * 0.125f + mk1;
            Sf[S_OFF + (r0 + 8) * S_PITCH + col] = acc[ni][2] * 0.125f + mk0;
            Sf[S_OFF + (r0 + 8) * S_PITCH + col + 1] = acc[ni][3] * 0.125f + mk1;
        }
        __syncthreads();
    }

    {
        float* Sf = (float*)su;
        for (int r = 0; r < 4; r++) {
            int row = wid * 4 + r;
            float* rp = Sf + S_OFF + row * S_PITCH;
            float mx = -1e30f;
            for (int m = lane; m < 1024; m += 32) mx = fmaxf(mx, rp[m]);
#pragma unroll
            for (int o = 16; o; o >>= 1) mx = fmaxf(mx, __shfl_xor_sync(0xffffffffu, mx, o));
            float sum = 0.0f;
            for (int m = lane; m < 1024; m += 64) {
                float a0 = rp[m] - mx;
                float a1 = rp[m + 32] - mx;
                float e0 = __expf(a0);
                float e1 = fexp(a1);
                rp[m] = e0;
                rp[m + 32] = e1;
                sum += e0 + e1;
            }
#pragma unroll
            for (int o = 16; o; o >>= 1) sum += __shfl_xor_sync(0xffffffffu, sum, o);
            if (lane == 0) s_inv32[row] = 1.0f / sum;
        }
    }
    __syncthreads();

    for (int idx = tid; idx < 32 * 1024; idx += 256) {
        int row = idx >> 10, m = idx & 1023;
        float e = ((float*)su)[S_OFF + row * S_PITCH + m] * s_inv32[row];
        Prow[(size_t)row * MM + m] = e;
        bf16 hh, ll;
        split_bf16(e, hh, ll);
        su[S_OFF + row * S_PITCH + m] =
            (uint32_t)*(uint16_t*)&hh | ((uint32_t)*(uint16_t*)&ll << 16);
    }
    __syncthreads();

    auto issueV = [&](int buf, int ch) {
        uint32_t base = smem0 + (KV_OFF + buf * KV_BUF) * 4;
        int m0 = ch << 7;
        for (int i = tid; i < 1024; i += 256) {
            int r = i >> 4, sg = i & 15;
            uint32_t d = base + (uint32_t)(r * 68 + sg * 4) * 4;
            CP16(d, Vhp + (size_t)r * MM + m0 + sg * 8);
            CP16(d + KV_PLANE * 4, Vlp + (size_t)r * MM + m0 + sg * 8);
        }
    };

    issueV(0, 0);
    CP_COMMIT();

    float oacc[2][4] = {};
    for (int ch = 0; ch < 8; ch++) {
        if (ch < 7) issueV((ch + 1) & 1, ch + 1);
        CP_COMMIT();
        CP_WAIT1();
        __syncthreads();

        uint32_t kvb = smem0 + (KV_OFF + (ch & 1) * KV_BUF) * 4;
        int m0 = ch << 7;
#pragma unroll
        for (int kk = 0; kk < 8; kk++) {
            int r0 = wr * 16 + g;
            int kbase = m0 + kk * 16 + t * 2;
            uint32_t u0, u1, ah[4], al[4];
            u0 = su[S_OFF + r0 * S_PITCH + kbase];
            u1 = su[S_OFF + r0 * S_PITCH + kbase + 1];
            ah[0] = __byte_perm(u0, u1, 0x5410); al[0] = __byte_perm(u0, u1, 0x7632);
            u0 = su[S_OFF + (r0 + 8) * S_PITCH + kbase];
            u1 = su[S_OFF + (r0 + 8) * S_PITCH + kbase + 1];
            ah[1] = __byte_perm(u0, u1, 0x5410); al[1] = __byte_perm(u0, u1, 0x7632);
            u0 = su[S_OFF + r0 * S_PITCH + kbase + 8];
            u1 = su[S_OFF + r0 * S_PITCH + kbase + 9];
            ah[2] = __byte_perm(u0, u1, 0x5410); al[2] = __byte_perm(u0, u1, 0x7632);
            u0 = su[S_OFF + (r0 + 8) * S_PITCH + kbase + 8];
            u1 = su[S_OFF + (r0 + 8) * S_PITCH + kbase + 9];
            ah[3] = __byte_perm(u0, u1, 0x5410); al[3] = __byte_perm(u0, u1, 0x7632);

            uint32_t vh[2][2], vl[2][2];
            uint32_t vb = kvb + (uint32_t)(wc * 16 * 272) + kk * 32 + voff_lane;
            ldsm_x4(vh[0][0], vh[0][1], vh[1][0], vh[1][1], vb);
            ldsm_x4(vl[0][0], vl[0][1], vl[1][0], vl[1][1], vb + KV_PLANE * 4);
#pragma unroll
            for (int ni = 0; ni < 2; ni++) mma_bf16(oacc[ni], ah, vh[ni]);
#pragma unroll
            for (int ni = 0; ni < 2; ni++) mma_bf16(oacc[ni], ah, vl[ni]);
#pragma unroll
            for (int ni = 0; ni < 2; ni++) mma_bf16(oacc[ni], al, vh[ni]);
        }
        __syncthreads();
    }

    int h = z & 15;
#pragma unroll
    for (int ni = 0; ni < 2; ni++) {
        int row = wr * 16 + g;
        int d = wc * 16 + ni * 8 + 2 * t;
        float* dst0 = g_O + ((size_t)(b * NN + n0 + row) * DD) + h * HD + d;
        float* dst1 = g_O + ((size_t)(b * NN + n0 + row + 8) * DD) + h * HD + d;
        *(float2*)dst0 = make_float2(oacc[ni][0], oacc[ni][1]);
        *(float2*)dst1 = make_float2(oacc[ni][2], oacc[ni][3]);
    }
}

// ---------------------------------------------------------------------------
// Mask decode (dtype-agnostic, verified R2)
// ---------------------------------------------------------------------------
__global__ void mask_decode_kernel(const unsigned int* __restrict__ mw) {
    __shared__ int s_u8;
    int tid = threadIdx.x;
    if (tid == 0) s_u8 = 0;
    __syncthreads();
    int u8 = 0;
    for (int i = tid; i < 1024; i += 256) {
        unsigned int w = mw[i];
        if (w > 1u && w != 0x3F800000u) u8 = 1;
    }
    if (u8) atomicOr(&s_u8, 1);
    __syncthreads();
    if (s_u8) {
        const unsigned char* mb = (const unsigned char*)mw;
        for (int i = tid; i < BB * MM; i += 256) g_maskadd[i] = mb[i] ? -1e30f : 0.0f;
    } else {
        for (int i = tid; i < BB * MM; i += 256) g_maskadd[i] = mw[i] ? -1e30f : 0.0f;
    }
}

// ---------------------------------------------------------------------------
// Q f32 [b,n,h*64+d] -> planes [b,h,n,d]
// ---------------------------------------------------------------------------
__global__ void convertQ_kernel() {
    int idx = blockIdx.x * 256 + threadIdx.x;
    if (idx >= BB * HH * NN * 16) return;
    int d4 = idx & 15;
    int n = (idx >> 4) & 1023;
    int bh = idx >> 14;
    int b = bh >> 4, h = bh & 15;
    float4 v = *(const float4*)(g_Q + ((size_t)(b * NN + n) * DD) + h * HD + d4 * 4);
    uint32_t h0, l0, h1, l1;
    bf16split2(v.x, v.y, h0, l0);
    bf16split2(v.z, v.w, h1, l1);
    size_t o = ((size_t)bh * NN + n) * 32 + d4 * 2;
    ((uint32_t*)g_Qph)[o] = h0;
    ((uint32_t*)g_Qph)[o + 1] = h1;
    ((uint32_t*)g_Qpl)[o] = l0;
    ((uint32_t*)g_Qpl)[o + 1] = l1;
}

// K f32 (c=0 slice of KV) -> planes [b,h,m,d]
__global__ void convertK_kernel() {
    int idx = blockIdx.x * 256 + threadIdx.x;
    if (idx >= BB * HH * MM * 16) return;
    int d4 = idx & 15;
    int m = (idx >> 4) & 1023;
    int bh = idx >> 14;
    int b = bh >> 4, h = bh & 15;
    float4 v = *(const float4*)(g_KV + ((size_t)(b * MM + m) * 2 * DD) + h * HD + d4 * 4);
    uint32_t h0, l0, h1, l1;
    bf16split2(v.x, v.y, h0, l0);
    bf16split2(v.z, v.w, h1, l1);
    size_t o = ((size_t)bh * MM + m) * 32 + d4 * 2;
    ((uint32_t*)g_Kph)[o] = h0;
    ((uint32_t*)g_Kph)[o + 1] = h1;
    ((uint32_t*)g_Kpl)[o] = l0;
    ((uint32_t*)g_Kpl)[o + 1] = l1;
}

// V^T planes: [b,h,d,m] = split(g_KV[b,m,1,h*64+d])
__global__ void transposeV_planes() {
    __shared__ float tbuf[32][33];
    int m0 = blockIdx.x * 32, d0 = blockIdx.y * 32, z = blockIdx.z;
    int b = z >> 4, h = z & 15;
    int tx = threadIdx.x, ty = threadIdx.y;
    for (int i = ty; i < 32; i += 8)
        tbuf[i][tx] = g_KV[((size_t)(b * MM + m0 + i) * 2 + 1) * DD + h * HD + d0 + tx];
    __syncthreads();
    for (int i = ty; i < 32; i += 8) {
        bf16 hh, ll;
        split_bf16(tbuf[tx][i], hh, ll);
        size_t o = ((size_t)z * HD + d0 + i) * MM + m0 + tx;
        g_Vth[o] = hh;
        g_Vtl[o] = ll;
    }
}

// ---------------------------------------------------------------------------
// Pure transpose: g_Pt[b,h,n,m] (exp'd) -> attn_out[b,n,m,h]
// ---------------------------------------------------------------------------
__global__ void transpose_kernel(float* __restrict__ attn_out) {
    extern __shared__ float sm[];  // [16][1025]
    int bn = blockIdx.x;
    int b = bn >> 10, n = bn & 1023;
    int tid = threadIdx.x;
    for (int idx = tid; idx < 16 * 1024; idx += 256) {
        int h = idx >> 10, m = idx & 1023;
        sm[h * 1025 + m] = g_Pt[((size_t)(b * HH + h) * NN + n) * MM + m];
    }
    __syncthreads();
    float* dst = attn_out + (size_t)bn * (MM * HH);
    for (int idx = tid; idx < 16 * 1024; idx += 256) {
        int m = idx >> 4, h = idx & 15;
        dst[idx] = sm[h * 1025 + m];
    }
}

// ---------------------------------------------------------------------------
// out[bn, 0:2] = O[bn, :] @ Wp + bp
// ---------------------------------------------------------------------------
__global__ void outproj_kernel(const float* __restrict__ Wp, const float* __restrict__ bp,
                               float* __restrict__ out) {
    int row = blockIdx.x;
    int tid = threadIdx.x;
    const float4* O4 = (const float4*)(g_O + (size_t)row * DD);
    float4 o = O4[tid];
    const float2* W2 = (const float2*)Wp;
    float2 w0 = W2[tid * 4 + 0];
    float2 w1 = W2[tid * 4 + 1];
    float2 w2 = W2[tid * 4 + 2];
    float2 w3 = W2[tid * 4 + 3];
    float a0 = o.x * w0.x + o.y * w1.x + o.z * w2.x + o.w * w3.x;
    float a1 = o.x * w0.y + o.y * w1.y + o.z * w2.y + o.w * w3.y;
    __shared__ float s0[256], s1[256];
    s0[tid] = a0;
    s1[tid] = a1;
    __syncthreads();
    for (int st = 128; st > 0; st >>= 1) {
        if (tid < st) {
            s0[tid] += s0[tid + st];
            s1[tid] += s1[tid + st];
        }
        __syncthreads();
    }
    if (tid == 0) {
        out[row * 2 + 0] = s0[0] + bp[0];
        out[row * 2 + 1] = s1[0] + bp[1];
    }
}

// ---------------------------------------------------------------------------
extern "C" void kernel_launch(void* const* d_in, const int* in_sizes, int n_in,
                              void* d_out, int out_size) {
    const float* query = (const float*)d_in[0];
    const float* key_value = (const float*)d_in[1];
    const unsigned int* mask_raw = (const unsigned int*)d_in[2];
    const float* Wq = (const float*)d_in[3];
    const float* bq = (const float*)d_in[4];
    const float* Wkv = (const float*)d_in[5];
    const float* bkv = (const float*)d_in[6];
    const float* Wp = (const float*)d_in[7];
    const float* bp = (const float*)d_in[8];

    float* out = (float*)d_out;           // outputs [4,1024,2]
    float* attn_out = out + BB * NN * 2;  // attention [4,1024,1024,16]

    float *Qp, *KVp;
    bf16 *WqTh, *WqTl, *WkvTh, *WkvTl, *Xh, *Xl;
    cudaGetSymbolAddress((void**)&Qp, g_Q);
    cudaGetSymbolAddress((void**)&KVp, g_KV);
    cudaGetSymbolAddress((void**)&WqTh, g_WqTh);
    cudaGetSymbolAddress((void**)&WqTl, g_WqTl);
    cudaGetSymbolAddress((void**)&WkvTh, g_WkvTh);
    cudaGetSymbolAddress((void**)&WkvTl, g_WkvTl);
    cudaGetSymbolAddress((void**)&Xh, g_Xh);
    cudaGetSymbolAddress((void**)&Xl, g_Xl);

    const int DYNPROJ = 3 * P_STAGE * 4;  // 122880 (3 stages x 40KB)
    cudaFuncSetAttribute(gemm_proj_kernel, cudaFuncAttributeMaxDynamicSharedMemorySize, DYNPROJ);
    cudaFuncSetAttribute(attn_fused_kernel, cudaFuncAttributeMaxDynamicSharedMemorySize, FUSED_SMEM);
    cudaFuncSetAttribute(transpose_kernel, cudaFuncAttributeMaxDynamicSharedMemorySize, TRANS_SMEM);

    // 0) mask decode + weight transposes (planes)
    mask_decode_kernel<<<1, 256>>>(mask_raw);
    transposeW_planes<<<dim3(DD / 32, DD / 32), dim3(32, 8)>>>(Wq, WqTh, WqTl, DD, DD);
    transposeW_planes<<<dim3(2 * DD / 32, DD / 32), dim3(32, 8)>>>(Wkv, WkvTh, WkvTl, DD, 2 * DD);

    // 1) Q = query @ Wq + bq (pre-split A planes)
    convert_split_kernel<<<BB * NN * DD / 4 / 256, 256>>>(query, Xh, Xl, BB * NN * DD / 4);
    gemm_proj_kernel<<<dim3(BB * NN / 128, DD / 128), 256, DYNPROJ>>>(
        Xh, Xl, WqTh, WqTl, bq, Qp, DD);
    // 2) KV = key_value @ Wkv + bkv
    convert_split_kernel<<<BB * MM * DD / 4 / 256, 256>>>(key_value, Xh, Xl, BB * MM * DD / 4);
    gemm_proj_kernel<<<dim3(BB * MM / 128, 2 * DD / 128), 256, DYNPROJ>>>(
        Xh, Xl, WkvTh, WkvTl, bkv, KVp, 2 * DD);
    // 3) plane conversions
    convertQ_kernel<<<BB * HH * NN * 16 / 256, 256>>>();
    convertK_kernel<<<BB * HH * MM * 16 / 256, 256>>>();
    transposeV_planes<<<dim3(MM / 32, HD / 32, BB * HH), dim3(32, 8)>>>();
    // 4) fused scores + softmax + P write + AV
    attn_fused_kernel<<<dim3(NN / 32, 1, BB * HH), 256, FUSED_SMEM>>>();
    // 5) attention output (pure transpose)
    transpose_kernel<<<BB * NN, 256, TRANS_SMEM>>>(attn_out);
    // 6) final projection
    outproj_kernel<<<BB * NN, 256>>>(Wp, bp, out);
}

// round 17
// speedup vs baseline: 1.1705x; 1.1705x over previous
#include <cuda_runtime.h>
#include <cuda_bf16.h>
#include <math.h>
#include <stdint.h>

#define BB 4
#define NN 1024
#define MM 1024
#define DD 1024
#define HH 16
#define HD 64

typedef __nv_bfloat16 bf16;

// ---------------------------------------------------------------------------
// Device scratch (no allocation allowed)
// ---------------------------------------------------------------------------
__device__ float g_Q[BB * NN * DD];                 // Q[b,n,h*64+d] (proj out)
__device__ float g_KV[BB * MM * 2 * DD];            // KV[b,m,c,h*64+d] (proj out)
__device__ float g_Pt[(size_t)BB * HH * NN * MM];   // exp'd probabilities [b,h,n,m]
__device__ float g_O[BB * NN * DD];                 // O[b,n,h*64+d]
__device__ float g_WqT[DD * DD];
__device__ float g_WkvT[2 * DD * DD];
__device__ bf16 g_Qph[BB * HH * NN * HD], g_Qpl[BB * HH * NN * HD];  // [b,h,n,d]
__device__ bf16 g_Kph[BB * HH * MM * HD], g_Kpl[BB * HH * MM * HD];  // [b,h,m,d]
__device__ bf16 g_Vth[BB * HH * HD * MM], g_Vtl[BB * HH * HD * MM];  // [b,h,d,m]
__device__ float g_maskadd[BB * MM];

#define TRANS_SMEM (16 * 1025 * 4)

// ---------------------------------------------------------------------------
// helpers
// ---------------------------------------------------------------------------
__device__ __forceinline__ uint32_t smem_to_u32(const void* p) {
    uint32_t a;
    asm("{ .reg .u64 t; cvta.to.shared.u64 t, %1; cvt.u32.u64 %0, t; }" : "=r"(a) : "l"(p));
    return a;
}
#define CP16(dst, src) \
    asm volatile("cp.async.cg.shared.global [%0], [%1], 16;" :: "r"(dst), "l"(src) : "memory")
#define CP_COMMIT() asm volatile("cp.async.commit_group;" ::: "memory")
#define CP_WAIT1() asm volatile("cp.async.wait_group 1;" ::: "memory")

__device__ __forceinline__ void bf16split2(float x, float y, uint32_t& h, uint32_t& l) {
    __nv_bfloat162 hb = __floats2bfloat162_rn(x, y);
    float rx = x - __bfloat162float(hb.x);
    float ry = y - __bfloat162float(hb.y);
    __nv_bfloat162 lb = __floats2bfloat162_rn(rx, ry);
    h = *(uint32_t*)&hb;
    l = *(uint32_t*)&lb;
}
__device__ __forceinline__ void split_bf16(float x, bf16& h, bf16& l) {
    h = __float2bfloat16_rn(x);
    l = __float2bfloat16_rn(x - __bfloat162float(h));
}
__device__ __forceinline__ void mma_bf16(float* c, const uint32_t* a, const uint32_t* b) {
    asm volatile(
        "mma.sync.aligned.m16n8k16.row.col.f32.bf16.bf16.f32 "
        "{%0,%1,%2,%3}, {%4,%5,%6,%7}, {%8,%9}, {%0,%1,%2,%3};"
        : "+f"(c[0]), "+f"(c[1]), "+f"(c[2]), "+f"(c[3])
        : "r"(a[0]), "r"(a[1]), "r"(a[2]), "r"(a[3]), "r"(b[0]), "r"(b[1]));
}
__device__ __forceinline__ void ldsm_x4(uint32_t& r0, uint32_t& r1, uint32_t& r2,
                                        uint32_t& r3, uint32_t addr) {
    asm volatile("ldmatrix.sync.aligned.m8n8.x4.shared.b16 {%0,%1,%2,%3}, [%4];"
                 : "=r"(r0), "=r"(r1), "=r"(r2), "=r"(r3) : "r"(addr));
}

// Fast exp on fma/alu pipes (no MUFU).
__device__ __forceinline__ float fexp(float x) {
    x = fmaxf(x, -87.0f);
    float t = x * 1.44269504088896f;
    float z = t + 12582912.0f;
    float nf = z - 12582912.0f;
    float f = t - nf;
    int sc = (((int)nf) + 127) << 23;
    float p = 0.009618129f;
    p = fmaf(p, f, 0.055490663f);
    p = fmaf(p, f, 0.240226507f);
    p = fmaf(p, f, 0.693147181f);
    p = fmaf(p, f, 1.0f);
    return p * __int_as_float(sc);
}

// ---------------------------------------------------------------------------
// Projection GEMM (R14/R15 proven: LDG->reg split->STS, ldmatrix, ILP MMA):
// C[128 x 128 tile] = A[.,1024] @ B^T + bias.
// smem stage (u32): Ah[128*20] Al[128*20] Bh[128*20] Bl[128*20], x2 stages.
// ---------------------------------------------------------------------------
#define P_ALOFF (128 * 20)
#define P_BOFF (2 * 128 * 20)
#define P_BLOFF (3 * 128 * 20)
#define P_STAGE (4 * 128 * 20)

__global__ void __launch_bounds__(256, 1)
gemm_proj_kernel(const float* __restrict__ A, const float* __restrict__ B,
                 const float* __restrict__ bias, float* __restrict__ C, long ldc) {
    extern __shared__ uint32_t smem_u[];
    int tid = threadIdx.x, wid = tid >> 5, lane = tid & 31;
    int row0 = blockIdx.x * 128, col0 = blockIdx.y * 128;
    int wc = wid & 3, wr = wid >> 2;
    int g = lane >> 2, t = lane & 3;
    uint32_t smem0 = smem_to_u32(smem_u);

    const float* Abase = A + (size_t)row0 * DD;
    const float* Bbase = B + (size_t)col0 * DD;

    int ra = tid >> 3, c4 = tid & 7;
    float4 pA[4], pB[4];
#define PREFETCH(k0)                                                            \
    do {                                                                        \
        _Pragma("unroll") for (int i = 0; i < 4; i++)                           \
            pA[i] = *(const float4*)(Abase + (size_t)(ra + i * 32) * DD + (k0) + c4 * 4); \
        _Pragma("unroll") for (int i = 0; i < 4; i++)                           \
            pB[i] = *(const float4*)(Bbase + (size_t)(ra + i * 32) * DD + (k0) + c4 * 4); \
    } while (0)
#define STORE_STAGE(buf)                                                        \
    do {                                                                        \
        uint32_t* st = smem_u + (buf) * P_STAGE;                                \
        _Pragma("unroll") for (int i = 0; i < 4; i++) {                         \
            float4 v = pA[i];                                                   \
            int r = ra + i * 32;                                                \
            uint32_t h0, l0, h1, l1;                                            \
            bf16split2(v.x, v.y, h0, l0);                                       \
            bf16split2(v.z, v.w, h1, l1);                                       \
            st[r * 20 + c4 * 2] = h0;           st[r * 20 + c4 * 2 + 1] = h1;   \
            st[P_ALOFF + r * 20 + c4 * 2] = l0; st[P_ALOFF + r * 20 + c4 * 2 + 1] = l1; \
        }                                                                       \
        _Pragma("unroll") for (int i = 0; i < 4; i++) {                         \
            float4 v = pB[i];                                                   \
            int r = ra + i * 32;                                                \
            uint32_t h0, l0, h1, l1;                                            \
            bf16split2(v.x, v.y, h0, l0);                                       \
            bf16split2(v.z, v.w, h1, l1);                                       \
            st[P_BOFF + r * 20 + c4 * 2] = h0;  st[P_BOFF + r * 20 + c4 * 2 + 1] = h1; \
            st[P_BLOFF + r * 20 + c4 * 2] = l0; st[P_BLOFF + r * 20 + c4 * 2 + 1] = l1; \
        }                                                                       \
    } while (0)

    uint32_t aoff_lane = (uint32_t)(lane & 15) * 80 + (lane >> 4) * 16;
    uint32_t boff_lane = (uint32_t)((((lane >> 4) & 1) * 8 + (lane & 7)) * 80) +
                         ((lane >> 3) & 1) * 16;

    float acc[4][4][4] = {};
    PREFETCH(0);
    STORE_STAGE(0);
    __syncthreads();

    for (int kt = 0; kt < 32; kt++) {
        int cur = kt & 1;
        if (kt + 1 < 32) PREFETCH((kt + 1) << 5);

        uint32_t stb = smem0 + cur * (P_STAGE * 4);
#pragma unroll
        for (int kk = 0; kk < 2; kk++) {
            uint32_t kb = kk * 32;
            uint32_t bh[4][2], bl[4][2];
            uint32_t bb = stb + P_BOFF * 4 + (uint32_t)(wc * 32 * 80) + kb + boff_lane;
            ldsm_x4(bh[0][0], bh[0][1], bh[1][0], bh[1][1], bb);
            ldsm_x4(bh[2][0], bh[2][1], bh[3][0], bh[3][1], bb + 16 * 80);
            ldsm_x4(bl[0][0], bl[0][1], bl[1][0], bl[1][1], bb + 128 * 20 * 4);
            ldsm_x4(bl[2][0], bl[2][1], bl[3][0], bl[3][1], bb + 128 * 20 * 4 + 16 * 80);
#pragma unroll
            for (int mi = 0; mi < 4; mi++) {
                uint32_t ab = stb + (uint32_t)((wr * 64 + mi * 16) * 80) + kb + aoff_lane;
                uint32_t ah[4], al[4];
                ldsm_x4(ah[0], ah[1], ah[2], ah[3], ab);
                ldsm_x4(al[0], al[1], al[2], al[3], ab + P_ALOFF * 4);
#pragma unroll
                for (int ni = 0; ni < 4; ni++) mma_bf16(acc[mi][ni], ah, bh[ni]);
#pragma unroll
                for (int ni = 0; ni < 4; ni++) mma_bf16(acc[mi][ni], ah, bl[ni]);
#pragma unroll
                for (int ni = 0; ni < 4; ni++) mma_bf16(acc[mi][ni], al, bh[ni]);
            }
        }
        if (kt + 1 < 32) STORE_STAGE(cur ^ 1);
        __syncthreads();
    }
#undef PREFETCH
#undef STORE_STAGE

#pragma unroll
    for (int mi = 0; mi < 4; mi++) {
#pragma unroll
        for (int ni = 0; ni < 4; ni++) {
            int row = row0 + wr * 64 + mi * 16 + g;
            int col = col0 + wc * 32 + ni * 8 + 2 * t;
            float2 bb = *(const float2*)(bias + col);
            float2 v0 = make_float2(acc[mi][ni][0] + bb.x, acc[mi][ni][1] + bb.y);
            float2 v1 = make_float2(acc[mi][ni][2] + bb.x, acc[mi][ni][3] + bb.y);
            *(float2*)(C + (size_t)row * ldc + col) = v0;
            *(float2*)(C + (size_t)(row + 8) * ldc + col) = v1;
        }
    }
}

// ---------------------------------------------------------------------------
// Fused attention: 32-row tiles, double-buffered K/V, ldmatrix everywhere.
// After softmax stats, S rows are repacked IN PLACE into bf16 hi/lo planes
// (hi at [1036r, +512), lo at [1036r+516, +512) words) so phase-2 A-fragments
// come from ldmatrix instead of scalar LDS + byte_perm.
// smem (u32): S[32][1036] | Qh[32][36] Ql[32][36] | 2 bufs x 2 planes x 4608 | mask[1024]
// ---------------------------------------------------------------------------
#define S_PITCH 1036
#define S_OFF 0
#define LO_OFF 516
#define QH_OFF (32 * S_PITCH)
#define QL_OFF (QH_OFF + 32 * 36)
#define KV_OFF (QL_OFF + 32 * 36)
#define KV_PLANE 4608
#define KV_BUF (2 * KV_PLANE)
#define MASK_OFF (KV_OFF + 2 * KV_BUF)
#define FUSED_U32 (MASK_OFF + 1024)
#define FUSED_SMEM (FUSED_U32 * 4)

__global__ void __launch_bounds__(256, 1) attn_fused_kernel() {
    extern __shared__ uint32_t su[];
    __shared__ float s_inv32[32];

    int tid = threadIdx.x, wid = tid >> 5, lane = tid & 31;
    int z = blockIdx.z;
    int b = z >> 4;
    int n0 = blockIdx.x * 32;
    int wr = wid >> 2, wc = wid & 3;
    int g = lane >> 2, t = lane & 3;
    uint32_t smem0 = smem_to_u32(su);

    const uint32_t* Qh32 = (const uint32_t*)g_Qph + ((size_t)z * NN + n0) * 32;
    const uint32_t* Ql32 = (const uint32_t*)g_Qpl + ((size_t)z * NN + n0) * 32;
    const bf16* Khp = g_Kph + (size_t)z * MM * HD;
    const bf16* Klp = g_Kpl + (size_t)z * MM * HD;
    const bf16* Vhp = g_Vth + (size_t)z * HD * MM;
    const bf16* Vlp = g_Vtl + (size_t)z * HD * MM;
    float* Prow = g_Pt + ((size_t)z * NN + n0) * MM;

    for (int i = tid; i < 32 * 32; i += 256) {
        int r = i >> 5, j = i & 31;
        su[QH_OFF + r * 36 + j] = Qh32[r * 32 + j];
        su[QL_OFF + r * 36 + j] = Ql32[r * 32 + j];
    }
    for (int i = tid; i < 1024; i += 256)
        ((float*)su)[MASK_OFF + i] = g_maskadd[b * MM + i];

    uint32_t koff_lane = (uint32_t)((((lane >> 4) & 1) * 8 + (lane & 7)) * 144) +
                         ((lane >> 3) & 1) * 16;
    uint32_t voff_lane = (uint32_t)((((lane >> 4) & 1) * 8 + (lane & 7)) * 272) +
                         ((lane >> 3) & 1) * 16;
    // A-operand lane offset for P planes (row pitch 1036 u32 = 4144 B)
    uint32_t poff_lane = (uint32_t)(lane & 15) * (S_PITCH * 4) + (lane >> 4) * 16;

    // ---------------- phase 1: scores ----------------
    auto issueK = [&](int buf, int ch) {
        uint32_t base = smem0 + (KV_OFF + buf * KV_BUF) * 4;
        int m0 = ch << 7;
        for (int i = tid; i < 1024; i += 256) {
            int r = i >> 3, sg = i & 7;
            uint32_t d = base + (uint32_t)(r * 36 + sg * 4) * 4;
            CP16(d, Khp + (size_t)(m0 + r) * HD + sg * 8);
            CP16(d + KV_PLANE * 4, Klp + (size_t)(m0 + r) * HD + sg * 8);
        }
    };

    issueK(0, 0);
    CP_COMMIT();
    __syncthreads();

    uint32_t qh[4][4], ql[4][4];
#pragma unroll
    for (int kk = 0; kk < 4; kk++) {
        int r = wr * 16 + g;
        int p = r * 36 + kk * 8 + t;
        qh[kk][0] = su[QH_OFF + p];          qh[kk][2] = su[QH_OFF + p + 4];
        qh[kk][1] = su[QH_OFF + p + 8 * 36]; qh[kk][3] = su[QH_OFF + p + 8 * 36 + 4];
        ql[kk][0] = su[QL_OFF + p];          ql[kk][2] = su[QL_OFF + p + 4];
        ql[kk][1] = su[QL_OFF + p + 8 * 36]; ql[kk][3] = su[QL_OFF + p + 8 * 36 + 4];
    }

    for (int ch = 0; ch < 8; ch++) {
        if (ch < 7) issueK((ch + 1) & 1, ch + 1);
        CP_COMMIT();
        CP_WAIT1();
        __syncthreads();

        uint32_t kvb = smem0 + (KV_OFF + (ch & 1) * KV_BUF) * 4;
        float acc[4][4] = {};
#pragma unroll
        for (int kk = 0; kk < 4; kk++) {
            uint32_t bh[4][2], bl[4][2];
            uint32_t bb = kvb + (uint32_t)(wc * 32 * 144) + kk * 32 + koff_lane;
            ldsm_x4(bh[0][0], bh[0][1], bh[1][0], bh[1][1], bb);
            ldsm_x4(bh[2][0], bh[2][1], bh[3][0], bh[3][1], bb + 16 * 144);
            ldsm_x4(bl[0][0], bl[0][1], bl[1][0], bl[1][1], bb + KV_PLANE * 4);
            ldsm_x4(bl[2][0], bl[2][1], bl[3][0], bl[3][1], bb + KV_PLANE * 4 + 16 * 144);
#pragma unroll
            for (int ni = 0; ni < 4; ni++) mma_bf16(acc[ni], qh[kk], bh[ni]);
#pragma unroll
            for (int ni = 0; ni < 4; ni++) mma_bf16(acc[ni], qh[kk], bl[ni]);
#pragma unroll
            for (int ni = 0; ni < 4; ni++) mma_bf16(acc[ni], ql[kk], bh[ni]);
        }
        int m0 = ch << 7;
        float* Sf = (float*)su;
#pragma unroll
        for (int ni = 0; ni < 4; ni++) {
            int col = m0 + wc * 32 + ni * 8 + 2 * t;
            float mk0 = ((float*)su)[MASK_OFF + col];
            float mk1 = ((float*)su)[MASK_OFF + col + 1];
            int r0 = wr * 16 + g;
            Sf[S_OFF + r0 * S_PITCH + col] = acc[ni][0] * 0.125f + mk0;
            Sf[S_OFF + r0 * S_PITCH + col + 1] = acc[ni][1] * 0.125f + mk1;
            Sf[S_OFF + (r0 + 8) * S_PITCH + col] = acc[ni][2] * 0.125f + mk0;
            Sf[S_OFF + (r0 + 8) * S_PITCH + col + 1] = acc[ni][3] * 0.125f + mk1;
        }
        __syncthreads();
    }

    // ---------------- softmax stats (each warp 4 rows, dual-pipe exp) --------
    {
        float* Sf = (float*)su;
        for (int r = 0; r < 4; r++) {
            int row = wid * 4 + r;
            float* rp = Sf + S_OFF + row * S_PITCH;
            float mx = -1e30f;
            for (int m = lane; m < 1024; m += 32) mx = fmaxf(mx, rp[m]);
#pragma unroll
            for (int o = 16; o; o >>= 1) mx = fmaxf(mx, __shfl_xor_sync(0xffffffffu, mx, o));
            float sum = 0.0f;
            for (int m = lane; m < 1024; m += 64) {
                float a0 = rp[m] - mx;
                float a1 = rp[m + 32] - mx;
                float e0 = __expf(a0);
                float e1 = fexp(a1);
                rp[m] = e0;
                rp[m + 32] = e1;
                sum += e0 + e1;
            }
#pragma unroll
            for (int o = 16; o; o >>= 1) sum += __shfl_xor_sync(0xffffffffu, sum, o);
            if (lane == 0) s_inv32[row] = 1.0f / sum;
        }
    }
    __syncthreads();

    // -------- normalize + write P + in-place repack to bf16 hi/lo planes ----
    // Row r: read f32 row (all threads), barrier, then write hi/lo planes into
    // the same row's word range (disjoint from other rows -> no extra barrier).
    {
        float* Sf = (float*)su;
        int m = tid * 4;
        for (int r = 0; r < 32; r++) {
            float4 v = *(float4*)&Sf[S_OFF + r * S_PITCH + m];
            __syncthreads();  // all reads of row r complete before overwrite
            float inv = s_inv32[r];
            v.x *= inv; v.y *= inv; v.z *= inv; v.w *= inv;
            *(float4*)&Prow[(size_t)r * MM + m] = v;
            bf16 h0, l0, h1, l1;
            uint32_t hi01, hi23, lo01, lo23;
            split_bf16(v.x, h0, l0);
            split_bf16(v.y, h1, l1);
            hi01 = (uint32_t)*(uint16_t*)&h0 | ((uint32_t)*(uint16_t*)&h1 << 16);
            lo01 = (uint32_t)*(uint16_t*)&l0 | ((uint32_t)*(uint16_t*)&l1 << 16);
            split_bf16(v.z, h0, l0);
            split_bf16(v.w, h1, l1);
            hi23 = (uint32_t)*(uint16_t*)&h0 | ((uint32_t)*(uint16_t*)&h1 << 16);
            lo23 = (uint32_t)*(uint16_t*)&l0 | ((uint32_t)*(uint16_t*)&l1 << 16);
            int w = r * S_PITCH + (m >> 1);
            su[w] = hi01;
            su[w + 1] = hi23;
            su[w + LO_OFF] = lo01;
            su[w + LO_OFF + 1] = lo23;
        }
    }
    __syncthreads();

    // ---------------- phase 2: O = P @ V^T (A via ldmatrix) ----------------
    auto issueV = [&](int buf, int ch) {
        uint32_t base = smem0 + (KV_OFF + buf * KV_BUF) * 4;
        int m0 = ch << 7;
        for (int i = tid; i < 1024; i += 256) {
            int r = i >> 4, sg = i & 15;
            uint32_t d = base + (uint32_t)(r * 68 + sg * 4) * 4;
            CP16(d, Vhp + (size_t)r * MM + m0 + sg * 8);
            CP16(d + KV_PLANE * 4, Vlp + (size_t)r * MM + m0 + sg * 8);
        }
    };

    issueV(0, 0);
    CP_COMMIT();

    float oacc[2][4] = {};
    uint32_t pbase = smem0 + (uint32_t)(wr * 16) * (S_PITCH * 4) + poff_lane;
    for (int ch = 0; ch < 8; ch++) {
        if (ch < 7) issueV((ch + 1) & 1, ch + 1);
        CP_COMMIT();
        CP_WAIT1();
        __syncthreads();

        uint32_t kvb = smem0 + (KV_OFF + (ch & 1) * KV_BUF) * 4;
        int m0 = ch << 7;
#pragma unroll
        for (int kk = 0; kk < 8; kk++) {
            uint32_t ab = pbase + (uint32_t)((m0 + kk * 16) * 2);
            uint32_t ah[4], al[4];
            ldsm_x4(ah[0], ah[1], ah[2], ah[3], ab);
            ldsm_x4(al[0], al[1], al[2], al[3], ab + LO_OFF * 4);

            uint32_t vh[2][2], vl[2][2];
            uint32_t vb = kvb + (uint32_t)(wc * 16 * 272) + kk * 32 + voff_lane;
            ldsm_x4(vh[0][0], vh[0][1], vh[1][0], vh[1][1], vb);
            ldsm_x4(vl[0][0], vl[0][1], vl[1][0], vl[1][1], vb + KV_PLANE * 4);
#pragma unroll
            for (int ni = 0; ni < 2; ni++) mma_bf16(oacc[ni], ah, vh[ni]);
#pragma unroll
            for (int ni = 0; ni < 2; ni++) mma_bf16(oacc[ni], ah, vl[ni]);
#pragma unroll
            for (int ni = 0; ni < 2; ni++) mma_bf16(oacc[ni], al, vh[ni]);
        }
        __syncthreads();
    }

    int h = z & 15;
#pragma unroll
    for (int ni = 0; ni < 2; ni++) {
        int row = wr * 16 + g;
        int d = wc * 16 + ni * 8 + 2 * t;
        float* dst0 = g_O + ((size_t)(b * NN + n0 + row) * DD) + h * HD + d;
        float* dst1 = g_O + ((size_t)(b * NN + n0 + row + 8) * DD) + h * HD + d;
        *(float2*)dst0 = make_float2(oacc[ni][0], oacc[ni][1]);
        *(float2*)dst1 = make_float2(oacc[ni][2], oacc[ni][3]);
    }
}

// ---------------------------------------------------------------------------
// Mask decode (dtype-agnostic, verified R2)
// ---------------------------------------------------------------------------
__global__ void mask_decode_kernel(const unsigned int* __restrict__ mw) {
    __shared__ int s_u8;
    int tid = threadIdx.x;
    if (tid == 0) s_u8 = 0;
    __syncthreads();
    int u8 = 0;
    for (int i = tid; i < 1024; i += 256) {
        unsigned int w = mw[i];
        if (w > 1u && w != 0x3F800000u) u8 = 1;
    }
    if (u8) atomicOr(&s_u8, 1);
    __syncthreads();
    if (s_u8) {
        const unsigned char* mb = (const unsigned char*)mw;
        for (int i = tid; i < BB * MM; i += 256) g_maskadd[i] = mb[i] ? -1e30f : 0.0f;
    } else {
        for (int i = tid; i < BB * MM; i += 256) g_maskadd[i] = mw[i] ? -1e30f : 0.0f;
    }
}

// ---------------------------------------------------------------------------
// Weight transpose (f32, verified R6)
// ---------------------------------------------------------------------------
__global__ void transposeW_kernel(const float* __restrict__ src, float* __restrict__ dst,
                                  int rows, int cols) {
    __shared__ float tbuf[32][33];
    int c0 = blockIdx.x * 32, r0 = blockIdx.y * 32;
    int tx = threadIdx.x, ty = threadIdx.y;
    for (int i = ty; i < 32; i += 8) tbuf[i][tx] = src[(size_t)(r0 + i) * cols + c0 + tx];
    __syncthreads();
    for (int i = ty; i < 32; i += 8) dst[(size_t)(c0 + i) * rows + r0 + tx] = tbuf[tx][i];
}

// ---------------------------------------------------------------------------
// Q f32 [b,n,h*64+d] -> planes [b,h,n,d]
// ---------------------------------------------------------------------------
__global__ void convertQ_kernel() {
    int idx = blockIdx.x * 256 + threadIdx.x;
    if (idx >= BB * HH * NN * 16) return;
    int d4 = idx & 15;
    int n = (idx >> 4) & 1023;
    int bh = idx >> 14;
    int b = bh >> 4, h = bh & 15;
    float4 v = *(const float4*)(g_Q + ((size_t)(b * NN + n) * DD) + h * HD + d4 * 4);
    uint32_t h0, l0, h1, l1;
    bf16split2(v.x, v.y, h0, l0);
    bf16split2(v.z, v.w, h1, l1);
    size_t o = ((size_t)bh * NN + n) * 32 + d4 * 2;
    ((uint32_t*)g_Qph)[o] = h0;
    ((uint32_t*)g_Qph)[o + 1] = h1;
    ((uint32_t*)g_Qpl)[o] = l0;
    ((uint32_t*)g_Qpl)[o + 1] = l1;
}

// K f32 (c=0 slice of KV) -> planes [b,h,m,d]
__global__ void convertK_kernel() {
    int idx = blockIdx.x * 256 + threadIdx.x;
    if (idx >= BB * HH * MM * 16) return;
    int d4 = idx & 15;
    int m = (idx >> 4) & 1023;
    int bh = idx >> 14;
    int b = bh >> 4, h = bh & 15;
    float4 v = *(const float4*)(g_KV + ((size_t)(b * MM + m) * 2 * DD) + h * HD + d4 * 4);
    uint32_t h0, l0, h1, l1;
    bf16split2(v.x, v.y, h0, l0);
    bf16split2(v.z, v.w, h1, l1);
    size_t o = ((size_t)bh * MM + m) * 32 + d4 * 2;
    ((uint32_t*)g_Kph)[o] = h0;
    ((uint32_t*)g_Kph)[o + 1] = h1;
    ((uint32_t*)g_Kpl)[o] = l0;
    ((uint32_t*)g_Kpl)[o + 1] = l1;
}

// V^T planes: [b,h,d,m] = split(g_KV[b,m,1,h*64+d])
__global__ void transposeV_planes() {
    __shared__ float tbuf[32][33];
    int m0 = blockIdx.x * 32, d0 = blockIdx.y * 32, z = blockIdx.z;
    int b = z >> 4, h = z & 15;
    int tx = threadIdx.x, ty = threadIdx.y;
    for (int i = ty; i < 32; i += 8)
        tbuf[i][tx] = g_KV[((size_t)(b * MM + m0 + i) * 2 + 1) * DD + h * HD + d0 + tx];
    __syncthreads();
    for (int i = ty; i < 32; i += 8) {
        bf16 hh, ll;
        split_bf16(tbuf[tx][i], hh, ll);
        size_t o = ((size_t)z * HD + d0 + i) * MM + m0 + tx;
        g_Vth[o] = hh;
        g_Vtl[o] = ll;
    }
}

// ---------------------------------------------------------------------------
// Pure transpose: g_Pt[b,h,n,m] (exp'd) -> attn_out[b,n,m,h]
// ---------------------------------------------------------------------------
__global__ void transpose_kernel(float* __restrict__ attn_out) {
    extern __shared__ float sm[];  // [16][1025]
    int bn = blockIdx.x;
    int b = bn >> 10, n = bn & 1023;
    int tid = threadIdx.x;
    for (int idx = tid; idx < 16 * 1024; idx += 256) {
        int h = idx >> 10, m = idx & 1023;
        sm[h * 1025 + m] = g_Pt[((size_t)(b * HH + h) * NN + n) * MM + m];
    }
    __syncthreads();
    float* dst = attn_out + (size_t)bn * (MM * HH);
    for (int idx = tid; idx < 16 * 1024; idx += 256) {
        int m = idx >> 4, h = idx & 15;
        dst[idx] = sm[h * 1025 + m];
    }
}

// ---------------------------------------------------------------------------
// out[bn, 0:2] = O[bn, :] @ Wp + bp
// ---------------------------------------------------------------------------
__global__ void outproj_kernel(const float* __restrict__ Wp, const float* __restrict__ bp,
                               float* __restrict__ out) {
    int row = blockIdx.x;
    int tid = threadIdx.x;
    const float4* O4 = (const float4*)(g_O + (size_t)row * DD);
    float4 o = O4[tid];
    const float2* W2 = (const float2*)Wp;
    float2 w0 = W2[tid * 4 + 0];
    float2 w1 = W2[tid * 4 + 1];
    float2 w2 = W2[tid * 4 + 2];
    float2 w3 = W2[tid * 4 + 3];
    float a0 = o.x * w0.x + o.y * w1.x + o.z * w2.x + o.w * w3.x;
    float a1 = o.x * w0.y + o.y * w1.y + o.z * w2.y + o.w * w3.y;
    __shared__ float s0[256], s1[256];
    s0[tid] = a0;
    s1[tid] = a1;
    __syncthreads();
    for (int st = 128; st > 0; st >>= 1) {
        if (tid < st) {
            s0[tid] += s0[tid + st];
            s1[tid] += s1[tid + st];
        }
        __syncthreads();
    }
    if (tid == 0) {
        out[row * 2 + 0] = s0[0] + bp[0];
        out[row * 2 + 1] = s1[0] + bp[1];
    }
}

// ---------------------------------------------------------------------------
extern "C" void kernel_launch(void* const* d_in, const int* in_sizes, int n_in,
                              void* d_out, int out_size) {
    const float* query = (const float*)d_in[0];
    const float* key_value = (const float*)d_in[1];
    const unsigned int* mask_raw = (const unsigned int*)d_in[2];
    const float* Wq = (const float*)d_in[3];
    const float* bq = (const float*)d_in[4];
    const float* Wkv = (const float*)d_in[5];
    const float* bkv = (const float*)d_in[6];
    const float* Wp = (const float*)d_in[7];
    const float* bp = (const float*)d_in[8];

    float* out = (float*)d_out;           // outputs [4,1024,2]
    float* attn_out = out + BB * NN * 2;  // attention [4,1024,1024,16]

    float *Qp, *KVp, *WqTp, *WkvTp;
    cudaGetSymbolAddress((void**)&Qp, g_Q);
    cudaGetSymbolAddress((void**)&KVp, g_KV);
    cudaGetSymbolAddress((void**)&WqTp, g_WqT);
    cudaGetSymbolAddress((void**)&WkvTp, g_WkvT);

    const int DYNPROJ = 2 * P_STAGE * 4;  // 81920
    cudaFuncSetAttribute(gemm_proj_kernel, cudaFuncAttributeMaxDynamicSharedMemorySize, DYNPROJ);
    cudaFuncSetAttribute(attn_fused_kernel, cudaFuncAttributeMaxDynamicSharedMemorySize, FUSED_SMEM);
    cudaFuncSetAttribute(transpose_kernel, cudaFuncAttributeMaxDynamicSharedMemorySize, TRANS_SMEM);

    // 0) mask decode + weight transposes
    mask_decode_kernel<<<1, 256>>>(mask_raw);
    transposeW_kernel<<<dim3(DD / 32, DD / 32), dim3(32, 8)>>>(Wq, WqTp, DD, DD);
    transposeW_kernel<<<dim3(2 * DD / 32, DD / 32), dim3(32, 8)>>>(Wkv, WkvTp, DD, 2 * DD);

    // 1) Q = query @ Wq + bq
    gemm_proj_kernel<<<dim3(BB * NN / 128, DD / 128), 256, DYNPROJ>>>(query, WqTp, bq, Qp, DD);
    // 2) KV = key_value @ Wkv + bkv
    gemm_proj_kernel<<<dim3(BB * MM / 128, 2 * DD / 128), 256, DYNPROJ>>>(key_value, WkvTp, bkv, KVp, 2 * DD);
    // 3) plane conversions
    convertQ_kernel<<<BB * HH * NN * 16 / 256, 256>>>();
    convertK_kernel<<<BB * HH * MM * 16 / 256, 256>>>();
    transposeV_planes<<<dim3(MM / 32, HD / 32, BB * HH), dim3(32, 8)>>>();
    // 4) fused scores + softmax + P write + AV (ldmatrix P-fragments)
    attn_fused_kernel<<<dim3(NN / 32, 1, BB * HH), 256, FUSED_SMEM>>>();
    // 5) attention output (pure transpose)
    transpose_kernel<<<BB * NN, 256, TRANS_SMEM>>>(attn_out);
    // 6) final projection
    outproj_kernel<<<BB * NN, 256>>>(Wp, bp, out);
}